// round 8
// baseline (speedup 1.0000x reference)
#include <cuda_runtime.h>
#include <cuda_bf16.h>
#include <cstdint>
#include <math.h>

// LSTM cell B=4096, I=H=1024, fused. mma.sync bf16 hi/lo split (3 MMAs).
// GEMM: 128x128x32 CTA tile, FOUR warps (2m x 2n, 64x64 each) to halve
// redundant smem fragment reads; 3-stage cp.async, XOR swizzle, 1 sync/iter,
// 2 CTAs/SM; fused LSTM epilogue with smem-staged coalesced I/O.
// (Resubmit of R7 — previous run died to a container infra failure, no data.)

#define BM 128
#define BN 128
#define BK 32
#define KTOT 2048
#define NITER (KTOT / BK)

// swizzled tiles: 128 rows x 64B, chunk' = chunk ^ ((row>>1)&3)
#define TILE_B 8192
#define OFF_AHI 0
#define OFF_ALO 8192
#define OFF_BHI 16384
#define OFF_BLO 24576
#define STAGE   32768
#define NSTAGE  3
#define SMEM_TOTAL (NSTAGE * STAGE)    // 98304 B -> 2 CTAs/SM

// epilogue staging overlays stage memory after mainloop
#define EPI_PITCH 36
#define H_OFF   0
#define C_OFF   (128 * EPI_PITCH * 4)      // 18432
#define CT_OFF  (2 * STAGE)                // stage-2 area (dead after mainloop)

__device__ __nv_bfloat16 g_Ahi[4096ull * 2048], g_Alo[4096ull * 2048];
__device__ __nv_bfloat16 g_Whi[4096ull * 2048], g_Wlo[4096ull * 2048];  // [n'][k]
__device__ float g_bias[4096];                                          // permuted bi+bh

__device__ __forceinline__ uint32_t smem_u32(const void* p) {
    uint32_t a;
    asm("{ .reg .u64 t; cvta.to.shared.u64 t, %1; cvt.u32.u64 %0, t; }" : "=r"(a) : "l"(p));
    return a;
}
__device__ __forceinline__ void cp_async16(uint32_t s, const void* g) {
    asm volatile("cp.async.cg.shared.global [%0], [%1], 16;\n" :: "r"(s), "l"(g));
}
#define CP_COMMIT() asm volatile("cp.async.commit_group;\n" ::: "memory")
#define CP_WAIT(n)  asm volatile("cp.async.wait_group %0;\n" :: "n"(n) : "memory")

__device__ __forceinline__ void ldsm_x4(uint32_t* r, uint32_t addr) {
    asm volatile("ldmatrix.sync.aligned.m8n8.x4.shared.b16 {%0,%1,%2,%3}, [%4];"
                 : "=r"(r[0]), "=r"(r[1]), "=r"(r[2]), "=r"(r[3]) : "r"(addr));
}
__device__ __forceinline__ void mma_bf16(float* c, const uint32_t* a, const uint32_t* b) {
    asm volatile("mma.sync.aligned.m16n8k16.row.col.f32.bf16.bf16.f32 "
                 "{%0,%1,%2,%3}, {%4,%5,%6,%7}, {%8,%9}, {%0,%1,%2,%3};"
                 : "+f"(c[0]), "+f"(c[1]), "+f"(c[2]), "+f"(c[3])
                 : "r"(a[0]), "r"(a[1]), "r"(a[2]), "r"(a[3]), "r"(b[0]), "r"(b[1]));
}
__device__ __forceinline__ float sigmoidf_fast(float v) {
    return 1.f / (1.f + __expf(-v));
}
__device__ __forceinline__ float tanhf_fast(float v) {
    return 2.f / (1.f + __expf(-2.f * v)) - 1.f;
}

// swizzled byte offset within a tile for (row, 16B-chunk)
__device__ __forceinline__ uint32_t swz(int row, int chunk) {
    return (uint32_t)(row * 64 + ((chunk ^ ((row >> 1) & 3)) << 4));
}

// ============================================================
__global__ __launch_bounds__(256)
void convert_a(const float* __restrict__ x, const float* __restrict__ h)
{
    const int idx = blockIdx.x * 256 + threadIdx.x;   // over 4096*512 float4
    const int m = idx >> 9;
    const int kq = idx & 511;
    float4 v = (kq < 256)
        ? reinterpret_cast<const float4*>(x)[(size_t)m * 256 + kq]
        : reinterpret_cast<const float4*>(h)[(size_t)m * 256 + (kq - 256)];
    __nv_bfloat16 h0 = __float2bfloat16(v.x), h1 = __float2bfloat16(v.y);
    __nv_bfloat16 h2 = __float2bfloat16(v.z), h3 = __float2bfloat16(v.w);
    __nv_bfloat16 l0 = __float2bfloat16(v.x - __bfloat162float(h0));
    __nv_bfloat16 l1 = __float2bfloat16(v.y - __bfloat162float(h1));
    __nv_bfloat16 l2 = __float2bfloat16(v.z - __bfloat162float(h2));
    __nv_bfloat16 l3 = __float2bfloat16(v.w - __bfloat162float(h3));
    __nv_bfloat162 hp0(h0, h1), hp1(h2, h3), lp0(l0, l1), lp1(l2, l3);
    uint2 hv, lv;
    hv.x = *reinterpret_cast<uint32_t*>(&hp0); hv.y = *reinterpret_cast<uint32_t*>(&hp1);
    lv.x = *reinterpret_cast<uint32_t*>(&lp0); lv.y = *reinterpret_cast<uint32_t*>(&lp1);
    reinterpret_cast<uint2*>(g_Ahi)[idx] = hv;
    reinterpret_cast<uint2*>(g_Alo)[idx] = lv;
}

// ============================================================
__global__ __launch_bounds__(256)
void convert_w(const float* __restrict__ wi, const float* __restrict__ wh,
               const float* __restrict__ bi, const float* __restrict__ bh)
{
    __shared__ float tile[32][33];
    const int k0 = blockIdx.x * 32;
    const int n0 = blockIdx.y * 32;     // 32 consecutive n' (8 hids x 4 gates)
    const int tx = threadIdx.x, ty = threadIdx.y;   // (32, 8)

    const int g_gate = tx >> 3;
    const int hid = (n0 >> 2) + (tx & 7);
    const int n_src = g_gate * 1024 + hid;
    const int cp = ((tx & 7) << 2) | g_gate;

    #pragma unroll
    for (int j = 0; j < 4; j++) {
        int k = k0 + ty + j * 8;
        const float* w = (k < 1024) ? (wi + (size_t)k * 4096) : (wh + (size_t)(k - 1024) * 4096);
        tile[ty + j * 8][cp] = w[n_src];
    }
    if (blockIdx.x == 0 && ty == 0)
        g_bias[n0 + cp] = bi[n_src] + bh[n_src];
    __syncthreads();

    #pragma unroll
    for (int j = 0; j < 4; j++) {
        int np = n0 + ty + j * 8;
        float v = tile[tx][ty + j * 8];
        __nv_bfloat16 hi = __float2bfloat16(v);
        __nv_bfloat16 lo = __float2bfloat16(v - __bfloat162float(hi));
        g_Whi[(size_t)np * 2048 + k0 + tx] = hi;
        g_Wlo[(size_t)np * 2048 + k0 + tx] = lo;
    }
}

// ============================================================
// GEMM + fused LSTM epilogue. 4 warps (64x64 each), 3-stage, 2 CTAs/SM.
// ============================================================
__global__ __launch_bounds__(128, 2)
void lstm_gemm_mma(const float* __restrict__ c_t, float* __restrict__ out)
{
    extern __shared__ char smem[];
    const uint32_t sb = smem_u32(smem);
    const int tid = threadIdx.x;
    const int lane = tid & 31;
    const int w = tid >> 5;             // 0..3
    const int wm0 = (w & 1) * 64;
    const int wn0 = (w >> 1) * 64;
    const int bm = blockIdx.y * BM;
    const int bn = blockIdx.x * BN;
    const int hid0 = bn >> 2;

    float acc[4][8][4];
    #pragma unroll
    for (int i = 0; i < 4; i++)
        #pragma unroll
        for (int j = 0; j < 8; j++)
            #pragma unroll
            for (int q = 0; q < 4; q++) acc[i][j][q] = 0.f;

    // loader: 512 chunks/tile, 4 per thread per tile (128 threads)
    auto load_stage = [&](int c, int buf) {
        const int kk = c * BK;
        const uint32_t st = sb + buf * STAGE;
        #pragma unroll
        for (int t = 0; t < 4; t++) {
            int idx = tid + t * 128;     // 0..511
            int row = idx >> 2;
            int c16 = idx & 3;
            uint32_t so = swz(row, c16);
            size_t ga = (size_t)(bm + row) * KTOT + kk + c16 * 8;
            size_t gb = (size_t)(bn + row) * KTOT + kk + c16 * 8;
            cp_async16(st + OFF_AHI + so, g_Ahi + ga);
            cp_async16(st + OFF_ALO + so, g_Alo + ga);
            cp_async16(st + OFF_BHI + so, g_Whi + gb);
            cp_async16(st + OFF_BLO + so, g_Wlo + gb);
        }
        CP_COMMIT();
    };

    const int rowA0 = wm0 + (lane & 15);                        // + tm*16
    const int rowB0 = wn0 + ((lane >> 4) << 3) + (lane & 7);    // + tn4*16
    const int cA = lane >> 4;
    const int cB = (lane >> 3) & 1;

    load_stage(0, 0);
    load_stage(1, 1);

    for (int c = 0; c < NITER; c++) {
        const int buf = c % NSTAGE;
        if (c + 1 < NITER) { CP_WAIT(1); } else { CP_WAIT(0); }
        __syncthreads();
        if (c + 2 < NITER) load_stage(c + 2, (c + 2) % NSTAGE);

        const uint32_t st = sb + buf * STAGE;
        #pragma unroll
        for (int ks = 0; ks < 2; ks++) {
            uint32_t ah[4][4], al[4][4];
            #pragma unroll
            for (int tm = 0; tm < 4; tm++) {
                uint32_t ra = swz(rowA0 + tm * 16, ks * 2 + cA);
                ldsm_x4(ah[tm], st + OFF_AHI + ra);
                ldsm_x4(al[tm], st + OFF_ALO + ra);
            }
            #pragma unroll
            for (int tn4 = 0; tn4 < 4; tn4++) {
                uint32_t rb = swz(rowB0 + tn4 * 16, ks * 2 + cB);
                uint32_t bh[4], bl[4];
                ldsm_x4(bh, st + OFF_BHI + rb);
                ldsm_x4(bl, st + OFF_BLO + rb);
                #pragma unroll
                for (int tm = 0; tm < 4; tm++) {
                    #pragma unroll
                    for (int s = 0; s < 2; s++) {
                        float* cc = acc[tm][tn4 * 2 + s];
                        mma_bf16(cc, ah[tm], &bh[2 * s]);   // hi*hi
                        mma_bf16(cc, ah[tm], &bl[2 * s]);   // hi*lo
                        mma_bf16(cc, al[tm], &bh[2 * s]);   // lo*hi
                    }
                }
            }
        }
    }

    // ---- load c_t tile into (dead) stage-2 area ----
    #pragma unroll
    for (int t = 0; t < 8; t++) {
        int idx = tid + t * 128;         // 0..1023
        int row = idx >> 3;
        int q = idx & 7;
        cp_async16(sb + CT_OFF + (uint32_t)(row * EPI_PITCH + q * 4) * 4,
                   c_t + (size_t)(bm + row) * 1024 + hid0 + q * 4);
    }
    CP_COMMIT();
    CP_WAIT(0);
    __syncthreads();

    float* ct_s = reinterpret_cast<float*>(smem + CT_OFF);
    float* h_s  = reinterpret_cast<float*>(smem + H_OFF);
    float* c_s  = reinterpret_cast<float*>(smem + C_OFF);

    const int quad = lane >> 2;
    const int tq = lane & 3;
    const bool evenq = (tq & 1) == 0;

    #pragma unroll
    for (int tm = 0; tm < 4; tm++) {
        const int m_l = wm0 + tm * 16 + quad + (evenq ? 0 : 8);
        #pragma unroll
        for (int tn = 0; tn < 8; tn++) {
            const int col0 = bn + wn0 + tn * 8;
            const float2 bv = *reinterpret_cast<const float2*>(&g_bias[col0 + 2 * tq]);
            float c0 = acc[tm][tn][0] + bv.x;
            float c1 = acc[tm][tn][1] + bv.y;
            float c2 = acc[tm][tn][2] + bv.x;
            float c3 = acc[tm][tn][3] + bv.y;
            float p0 = __shfl_xor_sync(0xffffffffu, c0, 1);
            float p1 = __shfl_xor_sync(0xffffffffu, c1, 1);
            float p2 = __shfl_xor_sync(0xffffffffu, c2, 1);
            float p3 = __shfl_xor_sync(0xffffffffu, c3, 1);
            float gi, gf, gg, go;
            if (evenq) { gi = c0; gf = c1; gg = p0; go = p1; }
            else       { gi = p2; gf = p3; gg = c2; go = c3; }
            const int hl = (wn0 >> 2) + tn * 2 + (tq >> 1);    // hid local 0..31
            const float ctv = ct_s[m_l * EPI_PITCH + hl];
            const float si = sigmoidf_fast(gi);
            const float sf = sigmoidf_fast(gf);
            const float so = sigmoidf_fast(go);
            const float tg = tanhf_fast(gg);
            const float cn = sf * ctv + si * tg;
            const float hn = so * tanhf_fast(cn);
            h_s[m_l * EPI_PITCH + hl] = hn;
            c_s[m_l * EPI_PITCH + hl] = cn;
        }
    }
    __syncthreads();

    #pragma unroll
    for (int t = 0; t < 8; t++) {
        int idx = tid + t * 128;
        int row = idx >> 3;
        int q = idx & 7;
        float4 hv = *reinterpret_cast<const float4*>(&h_s[row * EPI_PITCH + q * 4]);
        float4 cv = *reinterpret_cast<const float4*>(&c_s[row * EPI_PITCH + q * 4]);
        size_t o = (size_t)(bm + row) * 1024 + hid0 + q * 4;
        *reinterpret_cast<float4*>(&out[o]) = hv;
        *reinterpret_cast<float4*>(&out[4096ull * 1024 + o]) = cv;
    }
}

// ============================================================
extern "C" void kernel_launch(void* const* d_in, const int* in_sizes, int n_in,
                              void* d_out, int out_size)
{
    (void)in_sizes; (void)n_in; (void)out_size;
    const float* x  = (const float*)d_in[0];
    const float* ht = (const float*)d_in[1];
    const float* ct = (const float*)d_in[2];
    const float* wi = (const float*)d_in[3];
    const float* wh = (const float*)d_in[4];
    const float* bi = (const float*)d_in[5];
    const float* bh = (const float*)d_in[6];
    float* out = (float*)d_out;

    cudaFuncSetAttribute(lstm_gemm_mma, cudaFuncAttributeMaxDynamicSharedMemorySize, SMEM_TOTAL);

    convert_a<<<4096 * 512 / 256, 256>>>(x, ht);
    convert_w<<<dim3(2048 / 32, 4096 / 32), dim3(32, 8)>>>(wi, wh, bi, bh);
    lstm_gemm_mma<<<dim3(4096 / BN, 4096 / BM), 128, SMEM_TOTAL>>>(ct, out);
}

// round 10
// speedup vs baseline: 1.4271x; 1.4271x over previous
#include <cuda_runtime.h>
#include <cuda_fp16.h>
#include <cstdint>
#include <math.h>

// LSTM cell B=4096, I=H=1024, fused. fp16 one-sided split:
//   A = Ahi + Alo (fp16 pair, exact to ~2^-22), B truncated to fp16.
//   C = Ahi*B + Alo*B  (2 MMAs; error = B truncation only, ~1.5e-4 norm)
// GEMM: 128x128x32 tile, 8 warps (4m x 2n), 4-stage cp.async, XOR swizzle,
// 1 sync/iter, 2 CTAs/SM, fused LSTM epilogue (smem-staged coalesced I/O).
// R10 fix: __syncthreads() after mainloop before c_t staging (stage-3 buffer
// is reused as the c_t tile; without the barrier fast warps raced slow warps
// still reading stage 3 in iteration 63 -> NaN).

#define BM 128
#define BN 128
#define BK 32
#define KTOT 2048
#define NITER (KTOT / BK)

// swizzled tiles: 128 rows x 64B, chunk' = chunk ^ ((row>>1)&3)
#define TILE_B 8192
#define OFF_AHI 0
#define OFF_ALO 8192
#define OFF_B   16384
#define STAGE   24576
#define NSTAGE  4
#define SMEM_TOTAL (NSTAGE * STAGE)    // 98304 B -> 2 CTAs/SM

// epilogue staging overlays stage memory after mainloop
#define EPI_PITCH 36
#define H_OFF   0
#define C_OFF   (128 * EPI_PITCH * 4)      // 18432
#define CT_OFF  (3 * STAGE)                // stage-3 area (dead after mainloop + barrier)

__device__ __half g_Ahi[4096ull * 2048], g_Alo[4096ull * 2048];
__device__ __half g_Wf[4096ull * 2048];    // [n'][k], gate-interleaved
__device__ float g_bias[4096];             // permuted bi+bh

__device__ __forceinline__ uint32_t smem_u32(const void* p) {
    uint32_t a;
    asm("{ .reg .u64 t; cvta.to.shared.u64 t, %1; cvt.u32.u64 %0, t; }" : "=r"(a) : "l"(p));
    return a;
}
__device__ __forceinline__ void cp_async16(uint32_t s, const void* g) {
    asm volatile("cp.async.cg.shared.global [%0], [%1], 16;\n" :: "r"(s), "l"(g));
}
#define CP_COMMIT() asm volatile("cp.async.commit_group;\n" ::: "memory")
#define CP_WAIT(n)  asm volatile("cp.async.wait_group %0;\n" :: "n"(n) : "memory")

__device__ __forceinline__ void ldsm_x4(uint32_t* r, uint32_t addr) {
    asm volatile("ldmatrix.sync.aligned.m8n8.x4.shared.b16 {%0,%1,%2,%3}, [%4];"
                 : "=r"(r[0]), "=r"(r[1]), "=r"(r[2]), "=r"(r[3]) : "r"(addr));
}
__device__ __forceinline__ void mma_f16(float* c, const uint32_t* a, const uint32_t* b) {
    asm volatile("mma.sync.aligned.m16n8k16.row.col.f32.f16.f16.f32 "
                 "{%0,%1,%2,%3}, {%4,%5,%6,%7}, {%8,%9}, {%0,%1,%2,%3};"
                 : "+f"(c[0]), "+f"(c[1]), "+f"(c[2]), "+f"(c[3])
                 : "r"(a[0]), "r"(a[1]), "r"(a[2]), "r"(a[3]), "r"(b[0]), "r"(b[1]));
}
__device__ __forceinline__ float sigmoidf_fast(float v) {
    return 1.f / (1.f + __expf(-v));
}
__device__ __forceinline__ float tanhf_fast(float v) {
    return 2.f / (1.f + __expf(-2.f * v)) - 1.f;
}

// swizzled byte offset within a tile for (row, 16B-chunk)
__device__ __forceinline__ uint32_t swz(int row, int chunk) {
    return (uint32_t)(row * 64 + ((chunk ^ ((row >> 1) & 3)) << 4));
}

// ============================================================
// pre-kernel 1: A = [x|h] -> fp16 hi/lo, row-major [4096, 2048]
// ============================================================
__global__ __launch_bounds__(256)
void convert_a(const float* __restrict__ x, const float* __restrict__ h)
{
    const int idx = blockIdx.x * 256 + threadIdx.x;   // over 4096*512 float4
    const int m = idx >> 9;
    const int kq = idx & 511;
    float4 v = (kq < 256)
        ? reinterpret_cast<const float4*>(x)[(size_t)m * 256 + kq]
        : reinterpret_cast<const float4*>(h)[(size_t)m * 256 + (kq - 256)];
    __half h0 = __float2half(v.x), h1 = __float2half(v.y);
    __half h2 = __float2half(v.z), h3 = __float2half(v.w);
    __half l0 = __float2half(v.x - __half2float(h0));
    __half l1 = __float2half(v.y - __half2float(h1));
    __half l2 = __float2half(v.z - __half2float(h2));
    __half l3 = __float2half(v.w - __half2float(h3));
    __half2 hp0(h0, h1), hp1(h2, h3), lp0(l0, l1), lp1(l2, l3);
    uint2 hv, lv;
    hv.x = *reinterpret_cast<uint32_t*>(&hp0); hv.y = *reinterpret_cast<uint32_t*>(&hp1);
    lv.x = *reinterpret_cast<uint32_t*>(&lp0); lv.y = *reinterpret_cast<uint32_t*>(&lp1);
    reinterpret_cast<uint2*>(g_Ahi)[idx] = hv;
    reinterpret_cast<uint2*>(g_Alo)[idx] = lv;
}

// ============================================================
// pre-kernel 2: gate-interleaved transposed fp16 weights + permuted bias.
// Output row n' = hid*4 + gate; source col n = gate*1024 + hid.
// ============================================================
__global__ __launch_bounds__(256)
void convert_w(const float* __restrict__ wi, const float* __restrict__ wh,
               const float* __restrict__ bi, const float* __restrict__ bh)
{
    __shared__ float tile[32][33];
    const int k0 = blockIdx.x * 32;
    const int n0 = blockIdx.y * 32;     // 32 consecutive n' (8 hids x 4 gates)
    const int tx = threadIdx.x, ty = threadIdx.y;   // (32, 8)

    const int g_gate = tx >> 3;
    const int hid = (n0 >> 2) + (tx & 7);
    const int n_src = g_gate * 1024 + hid;
    const int cp = ((tx & 7) << 2) | g_gate;

    #pragma unroll
    for (int j = 0; j < 4; j++) {
        int k = k0 + ty + j * 8;
        const float* w = (k < 1024) ? (wi + (size_t)k * 4096) : (wh + (size_t)(k - 1024) * 4096);
        tile[ty + j * 8][cp] = w[n_src];
    }
    if (blockIdx.x == 0 && ty == 0)
        g_bias[n0 + cp] = bi[n_src] + bh[n_src];
    __syncthreads();

    #pragma unroll
    for (int j = 0; j < 4; j++) {
        int np = n0 + ty + j * 8;
        g_Wf[(size_t)np * 2048 + k0 + tx] = __float2half(tile[tx][ty + j * 8]);
    }
}

// ============================================================
// GEMM + fused LSTM epilogue. 8 warps (4m x 2n), 4-stage, 2 CTAs/SM.
// ============================================================
__global__ __launch_bounds__(256, 2)
void lstm_gemm_mma(const float* __restrict__ c_t, float* __restrict__ out)
{
    extern __shared__ char smem[];
    const uint32_t sb = smem_u32(smem);
    const int tid = threadIdx.x;
    const int lane = tid & 31;
    const int w = tid >> 5;
    const int wm0 = (w & 3) * 32;
    const int wn0 = (w >> 2) * 64;
    const int bm = blockIdx.y * BM;
    const int bn = blockIdx.x * BN;
    const int hid0 = bn >> 2;

    float acc[2][8][4];
    #pragma unroll
    for (int i = 0; i < 2; i++)
        #pragma unroll
        for (int j = 0; j < 8; j++)
            #pragma unroll
            for (int q = 0; q < 4; q++) acc[i][j][q] = 0.f;

    // loader: 3 tiles x 512 chunks -> 1536 cp16, 6 per thread
    auto load_stage = [&](int c, int buf) {
        const int kk = c * BK;
        const uint32_t st = sb + buf * STAGE;
        #pragma unroll
        for (int t = 0; t < 2; t++) {
            int idx = tid + t * 256;     // 0..511
            int row = idx >> 2;
            int c16 = idx & 3;
            uint32_t so = swz(row, c16);
            size_t ga = (size_t)(bm + row) * KTOT + kk + c16 * 8;
            size_t gb = (size_t)(bn + row) * KTOT + kk + c16 * 8;
            cp_async16(st + OFF_AHI + so, g_Ahi + ga);
            cp_async16(st + OFF_ALO + so, g_Alo + ga);
            cp_async16(st + OFF_B   + so, g_Wf  + gb);
        }
        CP_COMMIT();
    };

    const int rowA0 = wm0 + (lane & 15);                        // + tm*16
    const int rowB0 = wn0 + ((lane >> 4) << 3) + (lane & 7);    // + tn4*16
    const int cA = lane >> 4;
    const int cB = (lane >> 3) & 1;

    load_stage(0, 0);
    load_stage(1, 1);
    load_stage(2, 2);

    for (int c = 0; c < NITER; c++) {
        const int buf = c % NSTAGE;
        if (c + 2 < NITER)      { CP_WAIT(2); }
        else if (c + 1 < NITER) { CP_WAIT(1); }
        else                    { CP_WAIT(0); }
        __syncthreads();
        if (c + 3 < NITER) load_stage(c + 3, (c + 3) % NSTAGE);

        const uint32_t st = sb + buf * STAGE;
        #pragma unroll
        for (int ks = 0; ks < 2; ks++) {
            uint32_t ah[2][4], al[2][4];
            #pragma unroll
            for (int tm = 0; tm < 2; tm++) {
                uint32_t ra = swz(rowA0 + tm * 16, ks * 2 + cA);
                ldsm_x4(ah[tm], st + OFF_AHI + ra);
                ldsm_x4(al[tm], st + OFF_ALO + ra);
            }
            #pragma unroll
            for (int tn4 = 0; tn4 < 4; tn4++) {
                uint32_t rb = swz(rowB0 + tn4 * 16, ks * 2 + cB);
                uint32_t bf[4];
                ldsm_x4(bf, st + OFF_B + rb);
                #pragma unroll
                for (int tm = 0; tm < 2; tm++) {
                    #pragma unroll
                    for (int s = 0; s < 2; s++) {
                        float* cc = acc[tm][tn4 * 2 + s];
                        mma_f16(cc, ah[tm], &bf[2 * s]);   // hi * B
                        mma_f16(cc, al[tm], &bf[2 * s]);   // lo * B
                    }
                }
            }
        }
    }

    // All warps must finish reading stage 3 (used by iteration 63) before
    // the c_t tile overwrites it.
    __syncthreads();

    // ---- load c_t tile into (now dead) stage-3 area ----
    #pragma unroll
    for (int t = 0; t < 4; t++) {
        int idx = tid + t * 256;         // 0..1023
        int row = idx >> 3;
        int q = idx & 7;
        cp_async16(sb + CT_OFF + (uint32_t)(row * EPI_PITCH + q * 4) * 4,
                   c_t + (size_t)(bm + row) * 1024 + hid0 + q * 4);
    }
    CP_COMMIT();
    CP_WAIT(0);
    __syncthreads();

    float* ct_s = reinterpret_cast<float*>(smem + CT_OFF);
    float* h_s  = reinterpret_cast<float*>(smem + H_OFF);
    float* c_s  = reinterpret_cast<float*>(smem + C_OFF);

    const int quad = lane >> 2;
    const int tq = lane & 3;
    const bool evenq = (tq & 1) == 0;

    #pragma unroll
    for (int tm = 0; tm < 2; tm++) {
        const int m_l = wm0 + tm * 16 + quad + (evenq ? 0 : 8);
        #pragma unroll
        for (int tn = 0; tn < 8; tn++) {
            const int col0 = bn + wn0 + tn * 8;
            const float2 bv = *reinterpret_cast<const float2*>(&g_bias[col0 + 2 * tq]);
            float c0 = acc[tm][tn][0] + bv.x;
            float c1 = acc[tm][tn][1] + bv.y;
            float c2 = acc[tm][tn][2] + bv.x;
            float c3 = acc[tm][tn][3] + bv.y;
            float p0 = __shfl_xor_sync(0xffffffffu, c0, 1);
            float p1 = __shfl_xor_sync(0xffffffffu, c1, 1);
            float p2 = __shfl_xor_sync(0xffffffffu, c2, 1);
            float p3 = __shfl_xor_sync(0xffffffffu, c3, 1);
            float gi, gf, gg, go;
            if (evenq) { gi = c0; gf = c1; gg = p0; go = p1; }
            else       { gi = p2; gf = p3; gg = c2; go = c3; }
            const int hl = (wn0 >> 2) + tn * 2 + (tq >> 1);    // hid local 0..31
            const float ctv = ct_s[m_l * EPI_PITCH + hl];
            const float si = sigmoidf_fast(gi);
            const float sf = sigmoidf_fast(gf);
            const float so = sigmoidf_fast(go);
            const float tg = tanhf_fast(gg);
            const float cn = sf * ctv + si * tg;
            const float hn = so * tanhf_fast(cn);
            h_s[m_l * EPI_PITCH + hl] = hn;
            c_s[m_l * EPI_PITCH + hl] = cn;
        }
    }
    __syncthreads();

    #pragma unroll
    for (int t = 0; t < 4; t++) {
        int idx = tid + t * 256;
        int row = idx >> 3;
        int q = idx & 7;
        float4 hv = *reinterpret_cast<const float4*>(&h_s[row * EPI_PITCH + q * 4]);
        float4 cv = *reinterpret_cast<const float4*>(&c_s[row * EPI_PITCH + q * 4]);
        size_t o = (size_t)(bm + row) * 1024 + hid0 + q * 4;
        *reinterpret_cast<float4*>(&out[o]) = hv;
        *reinterpret_cast<float4*>(&out[4096ull * 1024 + o]) = cv;
    }
}

// ============================================================
extern "C" void kernel_launch(void* const* d_in, const int* in_sizes, int n_in,
                              void* d_out, int out_size)
{
    (void)in_sizes; (void)n_in; (void)out_size;
    const float* x  = (const float*)d_in[0];
    const float* ht = (const float*)d_in[1];
    const float* ct = (const float*)d_in[2];
    const float* wi = (const float*)d_in[3];
    const float* wh = (const float*)d_in[4];
    const float* bi = (const float*)d_in[5];
    const float* bh = (const float*)d_in[6];
    float* out = (float*)d_out;

    cudaFuncSetAttribute(lstm_gemm_mma, cudaFuncAttributeMaxDynamicSharedMemorySize, SMEM_TOTAL);

    convert_a<<<4096 * 512 / 256, 256>>>(x, ht);
    convert_w<<<dim3(2048 / 32, 4096 / 32), dim3(32, 8)>>>(wi, wh, bi, bh);
    lstm_gemm_mma<<<dim3(4096 / BN, 4096 / BM), 256, SMEM_TOTAL>>>(ct, out);
}

// round 11
// speedup vs baseline: 2.2765x; 1.5952x over previous
#include <cuda_runtime.h>
#include <cuda_fp16.h>
#include <cstdint>
#include <math.h>

// LSTM cell B=4096, I=H=1024, fused. PURE fp16 GEMM (1 MMA):
//   A and B both truncated to fp16 (RN), fp32 accumulate.
//   Measured error with B-only truncation was 2.9e-4; A truncation adds an
//   independent equal-magnitude term -> predicted ~4.1e-4 (threshold 1e-3).
// GEMM: 128x128x32 tile, 8 warps (4m x 2n), 6-stage cp.async, XOR swizzle,
// 1 sync/iter, 2 CTAs/SM, fused LSTM epilogue (smem-staged coalesced I/O).

#define BM 128
#define BN 128
#define BK 32
#define KTOT 2048
#define NITER (KTOT / BK)

// swizzled tiles: 128 rows x 64B, chunk' = chunk ^ ((row>>1)&3)
#define TILE_B 8192
#define OFF_A 0
#define OFF_B 8192
#define STAGE 16384
#define NSTAGE 6
#define SMEM_TOTAL (NSTAGE * STAGE)    // 98304 B -> 2 CTAs/SM

// epilogue staging overlays stage memory after the post-mainloop barrier
#define EPI_PITCH 36
#define H_OFF   0
#define C_OFF   (128 * EPI_PITCH * 4)      // 18432
#define CT_OFF  (2 * 128 * EPI_PITCH * 4)  // 36864 (total 55296 < 98304)

__device__ __half g_Af[4096ull * 2048];    // [m][k] fp16
__device__ __half g_Wf[4096ull * 2048];    // [n'][k] fp16, gate-interleaved
__device__ float g_bias[4096];             // permuted bi+bh

__device__ __forceinline__ uint32_t smem_u32(const void* p) {
    uint32_t a;
    asm("{ .reg .u64 t; cvta.to.shared.u64 t, %1; cvt.u32.u64 %0, t; }" : "=r"(a) : "l"(p));
    return a;
}
__device__ __forceinline__ void cp_async16(uint32_t s, const void* g) {
    asm volatile("cp.async.cg.shared.global [%0], [%1], 16;\n" :: "r"(s), "l"(g));
}
#define CP_COMMIT() asm volatile("cp.async.commit_group;\n" ::: "memory")
#define CP_WAIT(n)  asm volatile("cp.async.wait_group %0;\n" :: "n"(n) : "memory")

__device__ __forceinline__ void ldsm_x4(uint32_t* r, uint32_t addr) {
    asm volatile("ldmatrix.sync.aligned.m8n8.x4.shared.b16 {%0,%1,%2,%3}, [%4];"
                 : "=r"(r[0]), "=r"(r[1]), "=r"(r[2]), "=r"(r[3]) : "r"(addr));
}
__device__ __forceinline__ void mma_f16(float* c, const uint32_t* a, const uint32_t* b) {
    asm volatile("mma.sync.aligned.m16n8k16.row.col.f32.f16.f16.f32 "
                 "{%0,%1,%2,%3}, {%4,%5,%6,%7}, {%8,%9}, {%0,%1,%2,%3};"
                 : "+f"(c[0]), "+f"(c[1]), "+f"(c[2]), "+f"(c[3])
                 : "r"(a[0]), "r"(a[1]), "r"(a[2]), "r"(a[3]), "r"(b[0]), "r"(b[1]));
}
__device__ __forceinline__ float sigmoidf_fast(float v) {
    return 1.f / (1.f + __expf(-v));
}
__device__ __forceinline__ float tanhf_fast(float v) {
    return 2.f / (1.f + __expf(-2.f * v)) - 1.f;
}

// swizzled byte offset within a tile for (row, 16B-chunk)
__device__ __forceinline__ uint32_t swz(int row, int chunk) {
    return (uint32_t)(row * 64 + ((chunk ^ ((row >> 1) & 3)) << 4));
}

// ============================================================
// pre-kernel 1: A = [x|h] -> fp16, row-major [4096, 2048]
// ============================================================
__global__ __launch_bounds__(256)
void convert_a(const float* __restrict__ x, const float* __restrict__ h)
{
    const int idx = blockIdx.x * 256 + threadIdx.x;   // over 4096*512 float4
    const int m = idx >> 9;
    const int kq = idx & 511;
    float4 v = (kq < 256)
        ? reinterpret_cast<const float4*>(x)[(size_t)m * 256 + kq]
        : reinterpret_cast<const float4*>(h)[(size_t)m * 256 + (kq - 256)];
    __half2 p0(__float2half(v.x), __float2half(v.y));
    __half2 p1(__float2half(v.z), __float2half(v.w));
    uint2 hv;
    hv.x = *reinterpret_cast<uint32_t*>(&p0);
    hv.y = *reinterpret_cast<uint32_t*>(&p1);
    reinterpret_cast<uint2*>(g_Af)[idx] = hv;
}

// ============================================================
// pre-kernel 2: gate-interleaved transposed fp16 weights + permuted bias.
// Output row n' = hid*4 + gate; source col n = gate*1024 + hid.
// ============================================================
__global__ __launch_bounds__(256)
void convert_w(const float* __restrict__ wi, const float* __restrict__ wh,
               const float* __restrict__ bi, const float* __restrict__ bh)
{
    __shared__ float tile[32][33];
    const int k0 = blockIdx.x * 32;
    const int n0 = blockIdx.y * 32;     // 32 consecutive n' (8 hids x 4 gates)
    const int tx = threadIdx.x, ty = threadIdx.y;   // (32, 8)

    const int g_gate = tx >> 3;
    const int hid = (n0 >> 2) + (tx & 7);
    const int n_src = g_gate * 1024 + hid;
    const int cp = ((tx & 7) << 2) | g_gate;

    #pragma unroll
    for (int j = 0; j < 4; j++) {
        int k = k0 + ty + j * 8;
        const float* w = (k < 1024) ? (wi + (size_t)k * 4096) : (wh + (size_t)(k - 1024) * 4096);
        tile[ty + j * 8][cp] = w[n_src];
    }
    if (blockIdx.x == 0 && ty == 0)
        g_bias[n0 + cp] = bi[n_src] + bh[n_src];
    __syncthreads();

    #pragma unroll
    for (int j = 0; j < 4; j++) {
        int np = n0 + ty + j * 8;
        g_Wf[(size_t)np * 2048 + k0 + tx] = __float2half(tile[tx][ty + j * 8]);
    }
}

// ============================================================
// GEMM + fused LSTM epilogue. 8 warps (4m x 2n), 6-stage, 2 CTAs/SM.
// ============================================================
__global__ __launch_bounds__(256, 2)
void lstm_gemm_mma(const float* __restrict__ c_t, float* __restrict__ out)
{
    extern __shared__ char smem[];
    const uint32_t sb = smem_u32(smem);
    const int tid = threadIdx.x;
    const int lane = tid & 31;
    const int w = tid >> 5;
    const int wm0 = (w & 3) * 32;
    const int wn0 = (w >> 2) * 64;
    const int bm = blockIdx.y * BM;
    const int bn = blockIdx.x * BN;
    const int hid0 = bn >> 2;

    float acc[2][8][4];
    #pragma unroll
    for (int i = 0; i < 2; i++)
        #pragma unroll
        for (int j = 0; j < 8; j++)
            #pragma unroll
            for (int q = 0; q < 4; q++) acc[i][j][q] = 0.f;

    // loader: 2 tiles x 512 chunks = 1024 cp16, 4 per thread
    auto load_stage = [&](int c, int buf) {
        const int kk = c * BK;
        const uint32_t st = sb + buf * STAGE;
        #pragma unroll
        for (int t = 0; t < 2; t++) {
            int idx = tid + t * 256;     // 0..511
            int row = idx >> 2;
            int c16 = idx & 3;
            uint32_t so = swz(row, c16);
            size_t ga = (size_t)(bm + row) * KTOT + kk + c16 * 8;
            size_t gb = (size_t)(bn + row) * KTOT + kk + c16 * 8;
            cp_async16(st + OFF_A + so, g_Af + ga);
            cp_async16(st + OFF_B + so, g_Wf + gb);
        }
        CP_COMMIT();
    };

    const int rowA0 = wm0 + (lane & 15);                        // + tm*16
    const int rowB0 = wn0 + ((lane >> 4) << 3) + (lane & 7);    // + tn4*16
    const int cA = lane >> 4;
    const int cB = (lane >> 3) & 1;

    load_stage(0, 0);
    load_stage(1, 1);
    load_stage(2, 2);
    load_stage(3, 3);
    load_stage(4, 4);

    for (int c = 0; c < NITER; c++) {
        const int buf = c % NSTAGE;
        if      (c + 4 < NITER) { CP_WAIT(4); }
        else if (c + 3 < NITER) { CP_WAIT(3); }
        else if (c + 2 < NITER) { CP_WAIT(2); }
        else if (c + 1 < NITER) { CP_WAIT(1); }
        else                    { CP_WAIT(0); }
        __syncthreads();
        if (c + 5 < NITER) load_stage(c + 5, (c + 5) % NSTAGE);

        const uint32_t st = sb + buf * STAGE;
        #pragma unroll
        for (int ks = 0; ks < 2; ks++) {
            uint32_t af[2][4];
            #pragma unroll
            for (int tm = 0; tm < 2; tm++) {
                uint32_t ra = swz(rowA0 + tm * 16, ks * 2 + cA);
                ldsm_x4(af[tm], st + OFF_A + ra);
            }
            #pragma unroll
            for (int tn4 = 0; tn4 < 4; tn4++) {
                uint32_t rb = swz(rowB0 + tn4 * 16, ks * 2 + cB);
                uint32_t bf[4];
                ldsm_x4(bf, st + OFF_B + rb);
                #pragma unroll
                for (int tm = 0; tm < 2; tm++) {
                    #pragma unroll
                    for (int s = 0; s < 2; s++) {
                        mma_f16(acc[tm][tn4 * 2 + s], af[tm], &bf[2 * s]);
                    }
                }
            }
        }
    }

    // All warps must finish reading their final stage before the epilogue
    // staging (which overlays stage memory) writes to it.
    __syncthreads();

    // ---- load c_t tile into the (now dead) stage area ----
    #pragma unroll
    for (int t = 0; t < 4; t++) {
        int idx = tid + t * 256;         // 0..1023
        int row = idx >> 3;
        int q = idx & 7;
        cp_async16(sb + CT_OFF + (uint32_t)(row * EPI_PITCH + q * 4) * 4,
                   c_t + (size_t)(bm + row) * 1024 + hid0 + q * 4);
    }
    CP_COMMIT();
    CP_WAIT(0);
    __syncthreads();

    float* ct_s = reinterpret_cast<float*>(smem + CT_OFF);
    float* h_s  = reinterpret_cast<float*>(smem + H_OFF);
    float* c_s  = reinterpret_cast<float*>(smem + C_OFF);

    const int quad = lane >> 2;
    const int tq = lane & 3;
    const bool evenq = (tq & 1) == 0;

    #pragma unroll
    for (int tm = 0; tm < 2; tm++) {
        const int m_l = wm0 + tm * 16 + quad + (evenq ? 0 : 8);
        #pragma unroll
        for (int tn = 0; tn < 8; tn++) {
            const int col0 = bn + wn0 + tn * 8;
            const float2 bv = *reinterpret_cast<const float2*>(&g_bias[col0 + 2 * tq]);
            float c0 = acc[tm][tn][0] + bv.x;
            float c1 = acc[tm][tn][1] + bv.y;
            float c2 = acc[tm][tn][2] + bv.x;
            float c3 = acc[tm][tn][3] + bv.y;
            float p0 = __shfl_xor_sync(0xffffffffu, c0, 1);
            float p1 = __shfl_xor_sync(0xffffffffu, c1, 1);
            float p2 = __shfl_xor_sync(0xffffffffu, c2, 1);
            float p3 = __shfl_xor_sync(0xffffffffu, c3, 1);
            float gi, gf, gg, go;
            if (evenq) { gi = c0; gf = c1; gg = p0; go = p1; }
            else       { gi = p2; gf = p3; gg = c2; go = c3; }
            const int hl = (wn0 >> 2) + tn * 2 + (tq >> 1);    // hid local 0..31
            const float ctv = ct_s[m_l * EPI_PITCH + hl];
            const float si = sigmoidf_fast(gi);
            const float sf = sigmoidf_fast(gf);
            const float so = sigmoidf_fast(go);
            const float tg = tanhf_fast(gg);
            const float cn = sf * ctv + si * tg;
            const float hn = so * tanhf_fast(cn);
            h_s[m_l * EPI_PITCH + hl] = hn;
            c_s[m_l * EPI_PITCH + hl] = cn;
        }
    }
    __syncthreads();

    #pragma unroll
    for (int t = 0; t < 4; t++) {
        int idx = tid + t * 256;
        int row = idx >> 3;
        int q = idx & 7;
        float4 hv = *reinterpret_cast<const float4*>(&h_s[row * EPI_PITCH + q * 4]);
        float4 cv = *reinterpret_cast<const float4*>(&c_s[row * EPI_PITCH + q * 4]);
        size_t o = (size_t)(bm + row) * 1024 + hid0 + q * 4;
        *reinterpret_cast<float4*>(&out[o]) = hv;
        *reinterpret_cast<float4*>(&out[4096ull * 1024 + o]) = cv;
    }
}

// ============================================================
extern "C" void kernel_launch(void* const* d_in, const int* in_sizes, int n_in,
                              void* d_out, int out_size)
{
    (void)in_sizes; (void)n_in; (void)out_size;
    const float* x  = (const float*)d_in[0];
    const float* ht = (const float*)d_in[1];
    const float* ct = (const float*)d_in[2];
    const float* wi = (const float*)d_in[3];
    const float* wh = (const float*)d_in[4];
    const float* bi = (const float*)d_in[5];
    const float* bh = (const float*)d_in[6];
    float* out = (float*)d_out;

    cudaFuncSetAttribute(lstm_gemm_mma, cudaFuncAttributeMaxDynamicSharedMemorySize, SMEM_TOTAL);

    convert_a<<<4096 * 512 / 256, 256>>>(x, ht);
    convert_w<<<dim3(2048 / 32, 4096 / 32), dim3(32, 8)>>>(wi, wh, bi, bh);
    lstm_gemm_mma<<<dim3(4096 / BN, 4096 / BM), 256, SMEM_TOTAL>>>(ct, out);
}

// round 12
// speedup vs baseline: 2.3670x; 1.0397x over previous
#include <cuda_runtime.h>
#include <cuda_fp16.h>
#include <cstdint>
#include <math.h>

// LSTM cell B=4096, I=H=1024, fused. PURE fp16 GEMM (1 MMA), fp32 accum.
// R12: BK 32->64 (128B smem rows, chunk^(row&7) swizzle): 32 mainloop
// iterations instead of 64 -> half the barriers, 2x ILP per body.
// 128x128x64 tile, 8 warps (4m x 2n), 3-stage cp.async, 2 CTAs/SM,
// fused LSTM epilogue (smem-staged coalesced I/O).

#define BM 128
#define BN 128
#define BK 64
#define KTOT 2048
#define NITER (KTOT / BK)              // 32

// swizzled tiles: 128 rows x 128B, chunk' = chunk ^ (row&7)
#define TILE_B 16384
#define OFF_A 0
#define OFF_B 16384
#define STAGE 32768
#define NSTAGE 3
#define SMEM_TOTAL (NSTAGE * STAGE)    // 98304 B -> 2 CTAs/SM

// epilogue staging overlays stage memory after the post-mainloop barrier
#define EPI_PITCH 36
#define H_OFF   0
#define C_OFF   (128 * EPI_PITCH * 4)      // 18432
#define CT_OFF  (2 * STAGE)                // 65536 (stage-2 area, dead after barrier)

__device__ __half g_Af[4096ull * 2048];    // [m][k] fp16
__device__ __half g_Wf[4096ull * 2048];    // [n'][k] fp16, gate-interleaved
__device__ float g_bias[4096];             // permuted bi+bh

__device__ __forceinline__ uint32_t smem_u32(const void* p) {
    uint32_t a;
    asm("{ .reg .u64 t; cvta.to.shared.u64 t, %1; cvt.u32.u64 %0, t; }" : "=r"(a) : "l"(p));
    return a;
}
__device__ __forceinline__ void cp_async16(uint32_t s, const void* g) {
    asm volatile("cp.async.cg.shared.global [%0], [%1], 16;\n" :: "r"(s), "l"(g));
}
#define CP_COMMIT() asm volatile("cp.async.commit_group;\n" ::: "memory")
#define CP_WAIT(n)  asm volatile("cp.async.wait_group %0;\n" :: "n"(n) : "memory")

__device__ __forceinline__ void ldsm_x4(uint32_t* r, uint32_t addr) {
    asm volatile("ldmatrix.sync.aligned.m8n8.x4.shared.b16 {%0,%1,%2,%3}, [%4];"
                 : "=r"(r[0]), "=r"(r[1]), "=r"(r[2]), "=r"(r[3]) : "r"(addr));
}
__device__ __forceinline__ void mma_f16(float* c, const uint32_t* a, const uint32_t* b) {
    asm volatile("mma.sync.aligned.m16n8k16.row.col.f32.f16.f16.f32 "
                 "{%0,%1,%2,%3}, {%4,%5,%6,%7}, {%8,%9}, {%0,%1,%2,%3};"
                 : "+f"(c[0]), "+f"(c[1]), "+f"(c[2]), "+f"(c[3])
                 : "r"(a[0]), "r"(a[1]), "r"(a[2]), "r"(a[3]), "r"(b[0]), "r"(b[1]));
}
__device__ __forceinline__ float sigmoidf_fast(float v) {
    return 1.f / (1.f + __expf(-v));
}
__device__ __forceinline__ float tanhf_fast(float v) {
    return 2.f / (1.f + __expf(-2.f * v)) - 1.f;
}

// swizzled byte offset within a tile for (row, 16B-chunk 0..7)
__device__ __forceinline__ uint32_t swz(int row, int chunk) {
    return (uint32_t)(row * 128 + ((chunk ^ (row & 7)) << 4));
}

// ============================================================
// pre-kernel 1: A = [x|h] -> fp16, row-major [4096, 2048]
// ============================================================
__global__ __launch_bounds__(256)
void convert_a(const float* __restrict__ x, const float* __restrict__ h)
{
    const int idx = blockIdx.x * 256 + threadIdx.x;   // over 4096*512 float4
    const int m = idx >> 9;
    const int kq = idx & 511;
    float4 v = (kq < 256)
        ? reinterpret_cast<const float4*>(x)[(size_t)m * 256 + kq]
        : reinterpret_cast<const float4*>(h)[(size_t)m * 256 + (kq - 256)];
    __half2 p0(__float2half(v.x), __float2half(v.y));
    __half2 p1(__float2half(v.z), __float2half(v.w));
    uint2 hv;
    hv.x = *reinterpret_cast<uint32_t*>(&p0);
    hv.y = *reinterpret_cast<uint32_t*>(&p1);
    reinterpret_cast<uint2*>(g_Af)[idx] = hv;
}

// ============================================================
// pre-kernel 2: gate-interleaved transposed fp16 weights + permuted bias.
// Output row n' = hid*4 + gate; source col n = gate*1024 + hid.
// ============================================================
__global__ __launch_bounds__(256)
void convert_w(const float* __restrict__ wi, const float* __restrict__ wh,
               const float* __restrict__ bi, const float* __restrict__ bh)
{
    __shared__ float tile[32][33];
    const int k0 = blockIdx.x * 32;
    const int n0 = blockIdx.y * 32;     // 32 consecutive n' (8 hids x 4 gates)
    const int tx = threadIdx.x, ty = threadIdx.y;   // (32, 8)

    const int g_gate = tx >> 3;
    const int hid = (n0 >> 2) + (tx & 7);
    const int n_src = g_gate * 1024 + hid;
    const int cp = ((tx & 7) << 2) | g_gate;

    #pragma unroll
    for (int j = 0; j < 4; j++) {
        int k = k0 + ty + j * 8;
        const float* w = (k < 1024) ? (wi + (size_t)k * 4096) : (wh + (size_t)(k - 1024) * 4096);
        tile[ty + j * 8][cp] = w[n_src];
    }
    if (blockIdx.x == 0 && ty == 0)
        g_bias[n0 + cp] = bi[n_src] + bh[n_src];
    __syncthreads();

    #pragma unroll
    for (int j = 0; j < 4; j++) {
        int np = n0 + ty + j * 8;
        g_Wf[(size_t)np * 2048 + k0 + tx] = __float2half(tile[tx][ty + j * 8]);
    }
}

// ============================================================
// GEMM + fused LSTM epilogue. 8 warps (4m x 2n), BK=64, 3-stage, 2 CTAs/SM.
// ============================================================
__global__ __launch_bounds__(256, 2)
void lstm_gemm_mma(const float* __restrict__ c_t, float* __restrict__ out)
{
    extern __shared__ char smem[];
    const uint32_t sb = smem_u32(smem);
    const int tid = threadIdx.x;
    const int lane = tid & 31;
    const int w = tid >> 5;
    const int wm0 = (w & 3) * 32;
    const int wn0 = (w >> 2) * 64;
    const int bm = blockIdx.y * BM;
    const int bn = blockIdx.x * BN;
    const int hid0 = bn >> 2;

    float acc[2][8][4];
    #pragma unroll
    for (int i = 0; i < 2; i++)
        #pragma unroll
        for (int j = 0; j < 8; j++)
            #pragma unroll
            for (int q = 0; q < 4; q++) acc[i][j][q] = 0.f;

    // loader: 2 tiles x 1024 chunks = 2048 cp16, 8 per thread
    auto load_stage = [&](int c, int buf) {
        const int kk = c * BK;
        const uint32_t st = sb + buf * STAGE;
        #pragma unroll
        for (int t = 0; t < 4; t++) {
            int idx = tid + t * 256;     // 0..1023
            int row = idx >> 3;
            int c16 = idx & 7;
            uint32_t so = swz(row, c16);
            size_t ga = (size_t)(bm + row) * KTOT + kk + c16 * 8;
            size_t gb = (size_t)(bn + row) * KTOT + kk + c16 * 8;
            cp_async16(st + OFF_A + so, g_Af + ga);
            cp_async16(st + OFF_B + so, g_Wf + gb);
        }
        CP_COMMIT();
    };

    const int rowA0 = wm0 + (lane & 15);                        // + tm*16
    const int rowB0 = wn0 + ((lane >> 4) << 3) + (lane & 7);    // + tn4*16
    const int cA = lane >> 4;
    const int cB = (lane >> 3) & 1;

    load_stage(0, 0);
    load_stage(1, 1);

    for (int c = 0; c < NITER; c++) {
        const int buf = c % NSTAGE;
        if (c + 1 < NITER) { CP_WAIT(1); } else { CP_WAIT(0); }
        __syncthreads();
        if (c + 2 < NITER) load_stage(c + 2, (c + 2) % NSTAGE);

        const uint32_t st = sb + buf * STAGE;
        #pragma unroll
        for (int ks = 0; ks < 4; ks++) {
            uint32_t af[2][4];
            #pragma unroll
            for (int tm = 0; tm < 2; tm++) {
                uint32_t ra = swz(rowA0 + tm * 16, ks * 2 + cA);
                ldsm_x4(af[tm], st + OFF_A + ra);
            }
            #pragma unroll
            for (int tn4 = 0; tn4 < 4; tn4++) {
                uint32_t rb = swz(rowB0 + tn4 * 16, ks * 2 + cB);
                uint32_t bf[4];
                ldsm_x4(bf, st + OFF_B + rb);
                #pragma unroll
                for (int tm = 0; tm < 2; tm++) {
                    #pragma unroll
                    for (int s = 0; s < 2; s++) {
                        mma_f16(acc[tm][tn4 * 2 + s], af[tm], &bf[2 * s]);
                    }
                }
            }
        }
    }

    // All warps must finish reading their final stage before the epilogue
    // staging (which overlays stage memory) writes to it.
    __syncthreads();

    // ---- load c_t tile into the (now dead) stage area ----
    #pragma unroll
    for (int t = 0; t < 4; t++) {
        int idx = tid + t * 256;         // 0..1023
        int row = idx >> 3;
        int q = idx & 7;
        cp_async16(sb + CT_OFF + (uint32_t)(row * EPI_PITCH + q * 4) * 4,
                   c_t + (size_t)(bm + row) * 1024 + hid0 + q * 4);
    }
    CP_COMMIT();
    CP_WAIT(0);
    __syncthreads();

    float* ct_s = reinterpret_cast<float*>(smem + CT_OFF);
    float* h_s  = reinterpret_cast<float*>(smem + H_OFF);
    float* c_s  = reinterpret_cast<float*>(smem + C_OFF);

    const int quad = lane >> 2;
    const int tq = lane & 3;
    const bool evenq = (tq & 1) == 0;

    #pragma unroll
    for (int tm = 0; tm < 2; tm++) {
        const int m_l = wm0 + tm * 16 + quad + (evenq ? 0 : 8);
        #pragma unroll
        for (int tn = 0; tn < 8; tn++) {
            const int col0 = bn + wn0 + tn * 8;
            const float2 bv = *reinterpret_cast<const float2*>(&g_bias[col0 + 2 * tq]);
            float c0 = acc[tm][tn][0] + bv.x;
            float c1 = acc[tm][tn][1] + bv.y;
            float c2 = acc[tm][tn][2] + bv.x;
            float c3 = acc[tm][tn][3] + bv.y;
            float p0 = __shfl_xor_sync(0xffffffffu, c0, 1);
            float p1 = __shfl_xor_sync(0xffffffffu, c1, 1);
            float p2 = __shfl_xor_sync(0xffffffffu, c2, 1);
            float p3 = __shfl_xor_sync(0xffffffffu, c3, 1);
            float gi, gf, gg, go;
            if (evenq) { gi = c0; gf = c1; gg = p0; go = p1; }
            else       { gi = p2; gf = p3; gg = c2; go = c3; }
            const int hl = (wn0 >> 2) + tn * 2 + (tq >> 1);    // hid local 0..31
            const float ctv = ct_s[m_l * EPI_PITCH + hl];
            const float si = sigmoidf_fast(gi);
            const float sf = sigmoidf_fast(gf);
            const float so = sigmoidf_fast(go);
            const float tg = tanhf_fast(gg);
            const float cn = sf * ctv + si * tg;
            const float hn = so * tanhf_fast(cn);
            h_s[m_l * EPI_PITCH + hl] = hn;
            c_s[m_l * EPI_PITCH + hl] = cn;
        }
    }
    __syncthreads();

    #pragma unroll
    for (int t = 0; t < 4; t++) {
        int idx = tid + t * 256;
        int row = idx >> 3;
        int q = idx & 7;
        float4 hv = *reinterpret_cast<const float4*>(&h_s[row * EPI_PITCH + q * 4]);
        float4 cv = *reinterpret_cast<const float4*>(&c_s[row * EPI_PITCH + q * 4]);
        size_t o = (size_t)(bm + row) * 1024 + hid0 + q * 4;
        *reinterpret_cast<float4*>(&out[o]) = hv;
        *reinterpret_cast<float4*>(&out[4096ull * 1024 + o]) = cv;
    }
}

// ============================================================
extern "C" void kernel_launch(void* const* d_in, const int* in_sizes, int n_in,
                              void* d_out, int out_size)
{
    (void)in_sizes; (void)n_in; (void)out_size;
    const float* x  = (const float*)d_in[0];
    const float* ht = (const float*)d_in[1];
    const float* ct = (const float*)d_in[2];
    const float* wi = (const float*)d_in[3];
    const float* wh = (const float*)d_in[4];
    const float* bi = (const float*)d_in[5];
    const float* bh = (const float*)d_in[6];
    float* out = (float*)d_out;

    cudaFuncSetAttribute(lstm_gemm_mma, cudaFuncAttributeMaxDynamicSharedMemorySize, SMEM_TOTAL);

    convert_a<<<4096 * 512 / 256, 256>>>(x, ht);
    convert_w<<<dim3(2048 / 32, 4096 / 32), dim3(32, 8)>>>(wi, wh, bi, bh);
    lstm_gemm_mma<<<dim3(4096 / BN, 4096 / BM), 256, SMEM_TOTAL>>>(ct, out);
}

// round 15
// speedup vs baseline: 2.4274x; 1.0255x over previous
#include <cuda_runtime.h>
#include <cuda_fp16.h>
#include <cstdint>
#include <math.h>

// LSTM cell B=4096, I=H=1024, fused. PURE fp16 GEMM (1 MMA), fp32 accum.
// R13: (a) fragment loads batched per half-iteration (12 ldsm then 32 MMA)
//      to hide LDS latency behind a clean load-phase/compute-phase split;
//      (b) convert_a + convert_w merged into one launch.
// 128x128x64 tile, 8 warps (4m x 2n), 3-stage cp.async, 2 CTAs/SM,
// fused LSTM epilogue (smem-staged coalesced I/O).

#define BM 128
#define BN 128
#define BK 64
#define KTOT 2048
#define NITER (KTOT / BK)              // 32

// swizzled tiles: 128 rows x 128B, chunk' = chunk ^ (row&7)
#define TILE_B 16384
#define OFF_A 0
#define OFF_B 16384
#define STAGE 32768
#define NSTAGE 3
#define SMEM_TOTAL (NSTAGE * STAGE)    // 98304 B -> 2 CTAs/SM

// epilogue staging overlays stage memory after the post-mainloop barrier
#define EPI_PITCH 36
#define H_OFF   0
#define C_OFF   (128 * EPI_PITCH * 4)      // 18432
#define CT_OFF  (2 * STAGE)                // 65536 (stage-2, dead after barrier)

__device__ __half g_Af[4096ull * 2048];    // [m][k] fp16
__device__ __half g_Wf[4096ull * 2048];    // [n'][k] fp16, gate-interleaved
__device__ float g_bias[4096];             // permuted bi+bh

__device__ __forceinline__ uint32_t smem_u32(const void* p) {
    uint32_t a;
    asm("{ .reg .u64 t; cvta.to.shared.u64 t, %1; cvt.u32.u64 %0, t; }" : "=r"(a) : "l"(p));
    return a;
}
__device__ __forceinline__ void cp_async16(uint32_t s, const void* g) {
    asm volatile("cp.async.cg.shared.global [%0], [%1], 16;\n" :: "r"(s), "l"(g));
}
#define CP_COMMIT() asm volatile("cp.async.commit_group;\n" ::: "memory")
#define CP_WAIT(n)  asm volatile("cp.async.wait_group %0;\n" :: "n"(n) : "memory")

__device__ __forceinline__ void ldsm_x4(uint32_t* r, uint32_t addr) {
    asm volatile("ldmatrix.sync.aligned.m8n8.x4.shared.b16 {%0,%1,%2,%3}, [%4];"
                 : "=r"(r[0]), "=r"(r[1]), "=r"(r[2]), "=r"(r[3]) : "r"(addr));
}
__device__ __forceinline__ void mma_f16(float* c, const uint32_t* a, const uint32_t* b) {
    asm volatile("mma.sync.aligned.m16n8k16.row.col.f32.f16.f16.f32 "
                 "{%0,%1,%2,%3}, {%4,%5,%6,%7}, {%8,%9}, {%0,%1,%2,%3};"
                 : "+f"(c[0]), "+f"(c[1]), "+f"(c[2]), "+f"(c[3])
                 : "r"(a[0]), "r"(a[1]), "r"(a[2]), "r"(a[3]), "r"(b[0]), "r"(b[1]));
}
__device__ __forceinline__ float sigmoidf_fast(float v) {
    return 1.f / (1.f + __expf(-v));
}
__device__ __forceinline__ float tanhf_fast(float v) {
    return 2.f / (1.f + __expf(-2.f * v)) - 1.f;
}

// swizzled byte offset within a tile for (row, 16B-chunk 0..7)
__device__ __forceinline__ uint32_t swz(int row, int chunk) {
    return (uint32_t)(row * 128 + ((chunk ^ (row & 7)) << 4));
}

// ============================================================
// merged pre-kernel: blocks [0,8192) convert A; [8192,16384) convert W+bias.
// ============================================================
__global__ __launch_bounds__(256)
void convert_all(const float* __restrict__ x, const float* __restrict__ h,
                 const float* __restrict__ wi, const float* __restrict__ wh,
                 const float* __restrict__ bi, const float* __restrict__ bh)
{
    __shared__ float tile[32][33];
    const int tid = threadIdx.x;

    if (blockIdx.x < 8192) {
        // ---- A = [x|h] -> fp16, row-major [4096, 2048] ----
        const int idx = blockIdx.x * 256 + tid;       // over 4096*512 float4
        const int m = idx >> 9;
        const int kq = idx & 511;
        float4 v = (kq < 256)
            ? reinterpret_cast<const float4*>(x)[(size_t)m * 256 + kq]
            : reinterpret_cast<const float4*>(h)[(size_t)m * 256 + (kq - 256)];
        __half2 p0(__float2half(v.x), __float2half(v.y));
        __half2 p1(__float2half(v.z), __float2half(v.w));
        uint2 hv;
        hv.x = *reinterpret_cast<uint32_t*>(&p0);
        hv.y = *reinterpret_cast<uint32_t*>(&p1);
        reinterpret_cast<uint2*>(g_Af)[idx] = hv;
    } else {
        // ---- gate-interleaved transposed fp16 weights + permuted bias ----
        const int wb = blockIdx.x - 8192;             // 0..8191
        const int k0 = (wb & 63) * 32;
        const int n0 = (wb >> 6) * 32;                // 32 consecutive n'
        const int tx = tid & 31, ty = tid >> 5;       // (32, 8)

        const int g_gate = tx >> 3;
        const int hid = (n0 >> 2) + (tx & 7);
        const int n_src = g_gate * 1024 + hid;
        const int cp = ((tx & 7) << 2) | g_gate;

        #pragma unroll
        for (int j = 0; j < 4; j++) {
            int k = k0 + ty + j * 8;
            const float* w = (k < 1024) ? (wi + (size_t)k * 4096)
                                        : (wh + (size_t)(k - 1024) * 4096);
            tile[ty + j * 8][cp] = w[n_src];
        }
        if ((wb & 63) == 0 && ty == 0)
            g_bias[n0 + cp] = bi[n_src] + bh[n_src];
        __syncthreads();

        #pragma unroll
        for (int j = 0; j < 4; j++) {
            int np = n0 + ty + j * 8;
            g_Wf[(size_t)np * 2048 + k0 + tx] = __float2half(tile[tx][ty + j * 8]);
        }
    }
}

// ============================================================
// GEMM + fused LSTM epilogue. 8 warps (4m x 2n), BK=64, 3-stage, 2 CTAs/SM.
// ============================================================
__global__ __launch_bounds__(256, 2)
void lstm_gemm_mma(const float* __restrict__ c_t, float* __restrict__ out)
{
    extern __shared__ char smem[];
    const uint32_t sb = smem_u32(smem);
    const int tid = threadIdx.x;
    const int lane = tid & 31;
    const int w = tid >> 5;
    const int wm0 = (w & 3) * 32;
    const int wn0 = (w >> 2) * 64;
    const int bm = blockIdx.y * BM;
    const int bn = blockIdx.x * BN;
    const int hid0 = bn >> 2;

    float acc[2][8][4];
    #pragma unroll
    for (int i = 0; i < 2; i++)
        #pragma unroll
        for (int j = 0; j < 8; j++)
            #pragma unroll
            for (int q = 0; q < 4; q++) acc[i][j][q] = 0.f;

    // loader: 2 tiles x 1024 chunks = 2048 cp16, 8 per thread
    auto load_stage = [&](int c, int buf) {
        const int kk = c * BK;
        const uint32_t st = sb + buf * STAGE;
        #pragma unroll
        for (int t = 0; t < 4; t++) {
            int idx = tid + t * 256;     // 0..1023
            int row = idx >> 3;
            int c16 = idx & 7;
            uint32_t so = swz(row, c16);
            size_t ga = (size_t)(bm + row) * KTOT + kk + c16 * 8;
            size_t gb = (size_t)(bn + row) * KTOT + kk + c16 * 8;
            cp_async16(st + OFF_A + so, g_Af + ga);
            cp_async16(st + OFF_B + so, g_Wf + gb);
        }
        CP_COMMIT();
    };

    const int rowA0 = wm0 + (lane & 15);                        // + tm*16
    const int rowB0 = wn0 + ((lane >> 4) << 3) + (lane & 7);    // + tn4*16
    const int cA = lane >> 4;
    const int cB = (lane >> 3) & 1;

    load_stage(0, 0);
    load_stage(1, 1);

    for (int c = 0; c < NITER; c++) {
        const int buf = c % NSTAGE;
        if (c + 1 < NITER) { CP_WAIT(1); } else { CP_WAIT(0); }
        __syncthreads();
        if (c + 2 < NITER) load_stage(c + 2, (c + 2) % NSTAGE);

        const uint32_t st = sb + buf * STAGE;
        // two half-iterations; each: 12 ldsm batched, then 32 MMAs
        #pragma unroll
        for (int ksh = 0; ksh < 2; ksh++) {
            uint32_t af[2][2][4];      // [k2][tm]
            uint32_t bf[2][4][4];      // [k2][tn4]
            #pragma unroll
            for (int k2 = 0; k2 < 2; k2++) {
                const int ks = ksh * 2 + k2;
                #pragma unroll
                for (int tm = 0; tm < 2; tm++)
                    ldsm_x4(af[k2][tm], st + OFF_A + swz(rowA0 + tm * 16, ks * 2 + cA));
                #pragma unroll
                for (int tn4 = 0; tn4 < 4; tn4++)
                    ldsm_x4(bf[k2][tn4], st + OFF_B + swz(rowB0 + tn4 * 16, ks * 2 + cB));
            }
            #pragma unroll
            for (int k2 = 0; k2 < 2; k2++)
                #pragma unroll
                for (int tn4 = 0; tn4 < 4; tn4++)
                    #pragma unroll
                    for (int tm = 0; tm < 2; tm++)
                        #pragma unroll
                        for (int s = 0; s < 2; s++)
                            mma_f16(acc[tm][tn4 * 2 + s], af[k2][tm], &bf[k2][tn4][2 * s]);
        }
    }

    // All warps must finish reading their final stage before the epilogue
    // staging (which overlays stage memory) writes to it.
    __syncthreads();

    // ---- load c_t tile into the (now dead) stage area ----
    #pragma unroll
    for (int t = 0; t < 4; t++) {
        int idx = tid + t * 256;         // 0..1023
        int row = idx >> 3;
        int q = idx & 7;
        cp_async16(sb + CT_OFF + (uint32_t)(row * EPI_PITCH + q * 4) * 4,
                   c_t + (size_t)(bm + row) * 1024 + hid0 + q * 4);
    }
    CP_COMMIT();
    CP_WAIT(0);
    __syncthreads();

    float* ct_s = reinterpret_cast<float*>(smem + CT_OFF);
    float* h_s  = reinterpret_cast<float*>(smem + H_OFF);
    float* c_s  = reinterpret_cast<float*>(smem + C_OFF);

    const int quad = lane >> 2;
    const int tq = lane & 3;
    const bool evenq = (tq & 1) == 0;

    #pragma unroll
    for (int tm = 0; tm < 2; tm++) {
        const int m_l = wm0 + tm * 16 + quad + (evenq ? 0 : 8);
        #pragma unroll
        for (int tn = 0; tn < 8; tn++) {
            const int col0 = bn + wn0 + tn * 8;
            const float2 bv = *reinterpret_cast<const float2*>(&g_bias[col0 + 2 * tq]);
            float c0 = acc[tm][tn][0] + bv.x;
            float c1 = acc[tm][tn][1] + bv.y;
            float c2 = acc[tm][tn][2] + bv.x;
            float c3 = acc[tm][tn][3] + bv.y;
            float p0 = __shfl_xor_sync(0xffffffffu, c0, 1);
            float p1 = __shfl_xor_sync(0xffffffffu, c1, 1);
            float p2 = __shfl_xor_sync(0xffffffffu, c2, 1);
            float p3 = __shfl_xor_sync(0xffffffffu, c3, 1);
            float gi, gf, gg, go;
            if (evenq) { gi = c0; gf = c1; gg = p0; go = p1; }
            else       { gi = p2; gf = p3; gg = c2; go = c3; }
            const int hl = (wn0 >> 2) + tn * 2 + (tq >> 1);    // hid local 0..31
            const float ctv = ct_s[m_l * EPI_PITCH + hl];
            const float si = sigmoidf_fast(gi);
            const float sf = sigmoidf_fast(gf);
            const float so = sigmoidf_fast(go);
            const float tg = tanhf_fast(gg);
            const float cn = sf * ctv + si * tg;
            const float hn = so * tanhf_fast(cn);
            h_s[m_l * EPI_PITCH + hl] = hn;
            c_s[m_l * EPI_PITCH + hl] = cn;
        }
    }
    __syncthreads();

    #pragma unroll
    for (int t = 0; t < 4; t++) {
        int idx = tid + t * 256;
        int row = idx >> 3;
        int q = idx & 7;
        float4 hv = *reinterpret_cast<const float4*>(&h_s[row * EPI_PITCH + q * 4]);
        float4 cv = *reinterpret_cast<const float4*>(&c_s[row * EPI_PITCH + q * 4]);
        size_t o = (size_t)(bm + row) * 1024 + hid0 + q * 4;
        *reinterpret_cast<float4*>(&out[o]) = hv;
        *reinterpret_cast<float4*>(&out[4096ull * 1024 + o]) = cv;
    }
}

// ============================================================
extern "C" void kernel_launch(void* const* d_in, const int* in_sizes, int n_in,
                              void* d_out, int out_size)
{
    (void)in_sizes; (void)n_in; (void)out_size;
    const float* x  = (const float*)d_in[0];
    const float* ht = (const float*)d_in[1];
    const float* ct = (const float*)d_in[2];
    const float* wi = (const float*)d_in[3];
    const float* wh = (const float*)d_in[4];
    const float* bi = (const float*)d_in[5];
    const float* bh = (const float*)d_in[6];
    float* out = (float*)d_out;

    cudaFuncSetAttribute(lstm_gemm_mma, cudaFuncAttributeMaxDynamicSharedMemorySize, SMEM_TOTAL);

    convert_all<<<16384, 256>>>(x, ht, wi, wh, bi, bh);
    lstm_gemm_mma<<<dim3(4096 / BN, 4096 / BM), 256, SMEM_TOTAL>>>(ct, out);
}

// round 16
// speedup vs baseline: 2.4307x; 1.0014x over previous
#include <cuda_runtime.h>
#include <cuda_fp16.h>
#include <cstdint>
#include <math.h>

// LSTM cell B=4096, I=H=1024, fused. PURE fp16 GEMM (1 MMA), fp32 accum.
// R16: (a) ks-software-pipelined fragment loads (ldsm for ks+1 overlaps the
//      16 MMAs of ks -> tensor pipe stays fed within a stage);
//      (b) convert_w re-tiled to 64k x 128n' blocks: fully coalesced 128B
//      reads AND writes (was 32B-granular reads).
// 128x128x64 tile, 8 warps (4m x 2n), 3-stage cp.async, 2 CTAs/SM,
// fused LSTM epilogue (smem-staged coalesced I/O).

#define BM 128
#define BN 128
#define BK 64
#define KTOT 2048
#define NITER (KTOT / BK)              // 32

// swizzled tiles: 128 rows x 128B, chunk' = chunk ^ (row&7)
#define TILE_B 16384
#define OFF_A 0
#define OFF_B 16384
#define STAGE 32768
#define NSTAGE 3
#define SMEM_TOTAL (NSTAGE * STAGE)    // 98304 B -> 2 CTAs/SM

// epilogue staging overlays stage memory after the post-mainloop barrier
#define EPI_PITCH 36
#define H_OFF   0
#define C_OFF   (128 * EPI_PITCH * 4)      // 18432
#define CT_OFF  (2 * STAGE)                // 65536 (stage-2, dead after barrier)

#define NBLK_A 8192                        // convert grid split

__device__ __half g_Af[4096ull * 2048];    // [m][k] fp16
__device__ __half g_Wf[4096ull * 2048];    // [n'][k] fp16, gate-interleaved
__device__ float g_bias[4096];             // permuted bi+bh

__device__ __forceinline__ uint32_t smem_u32(const void* p) {
    uint32_t a;
    asm("{ .reg .u64 t; cvta.to.shared.u64 t, %1; cvt.u32.u64 %0, t; }" : "=r"(a) : "l"(p));
    return a;
}
__device__ __forceinline__ void cp_async16(uint32_t s, const void* g) {
    asm volatile("cp.async.cg.shared.global [%0], [%1], 16;\n" :: "r"(s), "l"(g));
}
#define CP_COMMIT() asm volatile("cp.async.commit_group;\n" ::: "memory")
#define CP_WAIT(n)  asm volatile("cp.async.wait_group %0;\n" :: "n"(n) : "memory")

__device__ __forceinline__ void ldsm_x4(uint32_t* r, uint32_t addr) {
    asm volatile("ldmatrix.sync.aligned.m8n8.x4.shared.b16 {%0,%1,%2,%3}, [%4];"
                 : "=r"(r[0]), "=r"(r[1]), "=r"(r[2]), "=r"(r[3]) : "r"(addr));
}
__device__ __forceinline__ void mma_f16(float* c, const uint32_t* a, const uint32_t* b) {
    asm volatile("mma.sync.aligned.m16n8k16.row.col.f32.f16.f16.f32 "
                 "{%0,%1,%2,%3}, {%4,%5,%6,%7}, {%8,%9}, {%0,%1,%2,%3};"
                 : "+f"(c[0]), "+f"(c[1]), "+f"(c[2]), "+f"(c[3])
                 : "r"(a[0]), "r"(a[1]), "r"(a[2]), "r"(a[3]), "r"(b[0]), "r"(b[1]));
}
__device__ __forceinline__ float sigmoidf_fast(float v) {
    return 1.f / (1.f + __expf(-v));
}
__device__ __forceinline__ float tanhf_fast(float v) {
    return 2.f / (1.f + __expf(-2.f * v)) - 1.f;
}

// swizzled byte offset within a tile for (row, 16B-chunk 0..7)
__device__ __forceinline__ uint32_t swz(int row, int chunk) {
    return (uint32_t)(row * 128 + ((chunk ^ (row & 7)) << 4));
}

// ============================================================
// merged pre-kernel:
//   blocks [0, 8192): A = [x|h] -> fp16 row-major [4096,2048]
//   blocks [8192, 9216): W transpose+gate-interleave, 64k x 128n' tiles
// ============================================================
__global__ __launch_bounds__(256)
void convert_all(const float* __restrict__ x, const float* __restrict__ h,
                 const float* __restrict__ wi, const float* __restrict__ wh,
                 const float* __restrict__ bi, const float* __restrict__ bh)
{
    __shared__ float tile[64][129];       // 33 KB
    const int tid = threadIdx.x;

    if (blockIdx.x < NBLK_A) {
        // ---- A conversion ----
        const int idx = blockIdx.x * 256 + tid;       // over 4096*512 float4
        const int m = idx >> 9;
        const int kq = idx & 511;
        float4 v = (kq < 256)
            ? reinterpret_cast<const float4*>(x)[(size_t)m * 256 + kq]
            : reinterpret_cast<const float4*>(h)[(size_t)m * 256 + (kq - 256)];
        __half2 p0(__float2half(v.x), __float2half(v.y));
        __half2 p1(__float2half(v.z), __float2half(v.w));
        uint2 hv;
        hv.x = *reinterpret_cast<uint32_t*>(&p0);
        hv.y = *reinterpret_cast<uint32_t*>(&p1);
        reinterpret_cast<uint2*>(g_Af)[idx] = hv;
    } else {
        // ---- W: 64 k-rows x 128 n'-cols per block ----
        const int wb = blockIdx.x - NBLK_A;           // 0..1023
        const int nb = wb >> 5;                       // 0..31
        const int kb = wb & 31;                       // 0..31
        const int hid0 = nb * 32;
        const int np0 = nb * 128;
        const int k0 = kb * 64;

        // read phase: lane j reads hid0+j for gate g, rows k (coalesced 128B)
        const int jlane = tid & 31;
        const int g_gate = (tid >> 5) & 3;
        const int kr = tid >> 7;                      // 0..1
        const int n_src = g_gate * 1024 + hid0 + jlane;
        #pragma unroll
        for (int kk = 0; kk < 32; kk++) {
            int kl = kr + kk * 2;                     // 0..63
            int k = k0 + kl;
            const float* w = (k < 1024) ? (wi + (size_t)k * 4096)
                                        : (wh + (size_t)(k - 1024) * 4096);
            tile[kl][jlane * 4 + g_gate] = w[n_src];
        }
        __syncthreads();

        // write phase: 2 threads per n' row, each 32 halves (64B), coalesced
        const int np_l = tid >> 1;                    // 0..127
        const int ksel = (tid & 1) * 32;
        uint32_t packed[16];
        #pragma unroll
        for (int q = 0; q < 16; q++) {
            float a = tile[ksel + q * 2 + 0][np_l];
            float b = tile[ksel + q * 2 + 1][np_l];
            __half2 p(__float2half(a), __float2half(b));
            packed[q] = *reinterpret_cast<uint32_t*>(&p);
        }
        uint4* dst = reinterpret_cast<uint4*>(&g_Wf[(size_t)(np0 + np_l) * 2048 + k0 + ksel]);
        #pragma unroll
        for (int q = 0; q < 4; q++)
            dst[q] = make_uint4(packed[q*4], packed[q*4+1], packed[q*4+2], packed[q*4+3]);

        // bias (once per n' block)
        if (kb == 0 && (tid & 1) == 0) {
            int np = np0 + np_l;
            int n_b = (np & 3) * 1024 + (np >> 2);
            g_bias[np] = bi[n_b] + bh[n_b];
        }
    }
}

// ============================================================
// GEMM + fused LSTM epilogue. 8 warps (4m x 2n), BK=64, 3-stage, 2 CTAs/SM.
// ks-software-pipelined fragments.
// ============================================================
__global__ __launch_bounds__(256, 2)
void lstm_gemm_mma(const float* __restrict__ c_t, float* __restrict__ out)
{
    extern __shared__ char smem[];
    const uint32_t sb = smem_u32(smem);
    const int tid = threadIdx.x;
    const int lane = tid & 31;
    const int w = tid >> 5;
    const int wm0 = (w & 3) * 32;
    const int wn0 = (w >> 2) * 64;
    const int bm = blockIdx.y * BM;
    const int bn = blockIdx.x * BN;
    const int hid0 = bn >> 2;

    float acc[2][8][4];
    #pragma unroll
    for (int i = 0; i < 2; i++)
        #pragma unroll
        for (int j = 0; j < 8; j++)
            #pragma unroll
            for (int q = 0; q < 4; q++) acc[i][j][q] = 0.f;

    // loader: 2 tiles x 1024 chunks = 2048 cp16, 8 per thread
    auto load_stage = [&](int c, int buf) {
        const int kk = c * BK;
        const uint32_t st = sb + buf * STAGE;
        #pragma unroll
        for (int t = 0; t < 4; t++) {
            int idx = tid + t * 256;     // 0..1023
            int row = idx >> 3;
            int c16 = idx & 7;
            uint32_t so = swz(row, c16);
            size_t ga = (size_t)(bm + row) * KTOT + kk + c16 * 8;
            size_t gb = (size_t)(bn + row) * KTOT + kk + c16 * 8;
            cp_async16(st + OFF_A + so, g_Af + ga);
            cp_async16(st + OFF_B + so, g_Wf + gb);
        }
        CP_COMMIT();
    };

    const int rowA0 = wm0 + (lane & 15);                        // + tm*16
    const int rowB0 = wn0 + ((lane >> 4) << 3) + (lane & 7);    // + tn4*16
    const int cA = lane >> 4;
    const int cB = (lane >> 3) & 1;

    load_stage(0, 0);
    load_stage(1, 1);

    for (int c = 0; c < NITER; c++) {
        const int buf = c % NSTAGE;
        if (c + 1 < NITER) { CP_WAIT(1); } else { CP_WAIT(0); }
        __syncthreads();
        if (c + 2 < NITER) load_stage(c + 2, (c + 2) % NSTAGE);

        const uint32_t st = sb + buf * STAGE;
        uint32_t af[2][2][4];      // [parity][tm]
        uint32_t bf[2][4][4];      // [parity][tn4]

        // software pipeline over ks: load ks+1 while issuing MMAs of ks
        #pragma unroll
        for (int tm = 0; tm < 2; tm++)
            ldsm_x4(af[0][tm], st + OFF_A + swz(rowA0 + tm * 16, cA));
        #pragma unroll
        for (int tn4 = 0; tn4 < 4; tn4++)
            ldsm_x4(bf[0][tn4], st + OFF_B + swz(rowB0 + tn4 * 16, cB));

        #pragma unroll
        for (int ks = 0; ks < 4; ks++) {
            const int cur = ks & 1, nxt = cur ^ 1;
            if (ks < 3) {
                #pragma unroll
                for (int tm = 0; tm < 2; tm++)
                    ldsm_x4(af[nxt][tm],
                            st + OFF_A + swz(rowA0 + tm * 16, (ks + 1) * 2 + cA));
                #pragma unroll
                for (int tn4 = 0; tn4 < 4; tn4++)
                    ldsm_x4(bf[nxt][tn4],
                            st + OFF_B + swz(rowB0 + tn4 * 16, (ks + 1) * 2 + cB));
            }
            #pragma unroll
            for (int tn4 = 0; tn4 < 4; tn4++)
                #pragma unroll
                for (int tm = 0; tm < 2; tm++)
                    #pragma unroll
                    for (int s = 0; s < 2; s++)
                        mma_f16(acc[tm][tn4 * 2 + s], af[cur][tm], &bf[cur][tn4][2 * s]);
        }
    }

    // All warps must finish reading their final stage before the epilogue
    // staging (which overlays stage memory) writes to it.
    __syncthreads();

    // ---- load c_t tile into the (now dead) stage area ----
    #pragma unroll
    for (int t = 0; t < 4; t++) {
        int idx = tid + t * 256;         // 0..1023
        int row = idx >> 3;
        int q = idx & 7;
        cp_async16(sb + CT_OFF + (uint32_t)(row * EPI_PITCH + q * 4) * 4,
                   c_t + (size_t)(bm + row) * 1024 + hid0 + q * 4);
    }
    CP_COMMIT();
    CP_WAIT(0);
    __syncthreads();

    float* ct_s = reinterpret_cast<float*>(smem + CT_OFF);
    float* h_s  = reinterpret_cast<float*>(smem + H_OFF);
    float* c_s  = reinterpret_cast<float*>(smem + C_OFF);

    const int quad = lane >> 2;
    const int tq = lane & 3;
    const bool evenq = (tq & 1) == 0;

    #pragma unroll
    for (int tm = 0; tm < 2; tm++) {
        const int m_l = wm0 + tm * 16 + quad + (evenq ? 0 : 8);
        #pragma unroll
        for (int tn = 0; tn < 8; tn++) {
            const int col0 = bn + wn0 + tn * 8;
            const float2 bv = *reinterpret_cast<const float2*>(&g_bias[col0 + 2 * tq]);
            float c0 = acc[tm][tn][0] + bv.x;
            float c1 = acc[tm][tn][1] + bv.y;
            float c2 = acc[tm][tn][2] + bv.x;
            float c3 = acc[tm][tn][3] + bv.y;
            float p0 = __shfl_xor_sync(0xffffffffu, c0, 1);
            float p1 = __shfl_xor_sync(0xffffffffu, c1, 1);
            float p2 = __shfl_xor_sync(0xffffffffu, c2, 1);
            float p3 = __shfl_xor_sync(0xffffffffu, c3, 1);
            float gi, gf, gg, go;
            if (evenq) { gi = c0; gf = c1; gg = p0; go = p1; }
            else       { gi = p2; gf = p3; gg = c2; go = c3; }
            const int hl = (wn0 >> 2) + tn * 2 + (tq >> 1);    // hid local 0..31
            const float ctv = ct_s[m_l * EPI_PITCH + hl];
            const float si = sigmoidf_fast(gi);
            const float sf = sigmoidf_fast(gf);
            const float so = sigmoidf_fast(go);
            const float tg = tanhf_fast(gg);
            const float cn = sf * ctv + si * tg;
            const float hn = so * tanhf_fast(cn);
            h_s[m_l * EPI_PITCH + hl] = hn;
            c_s[m_l * EPI_PITCH + hl] = cn;
        }
    }
    __syncthreads();

    #pragma unroll
    for (int t = 0; t < 4; t++) {
        int idx = tid + t * 256;
        int row = idx >> 3;
        int q = idx & 7;
        float4 hv = *reinterpret_cast<const float4*>(&h_s[row * EPI_PITCH + q * 4]);
        float4 cv = *reinterpret_cast<const float4*>(&c_s[row * EPI_PITCH + q * 4]);
        size_t o = (size_t)(bm + row) * 1024 + hid0 + q * 4;
        *reinterpret_cast<float4*>(&out[o]) = hv;
        *reinterpret_cast<float4*>(&out[4096ull * 1024 + o]) = cv;
    }
}

// ============================================================
extern "C" void kernel_launch(void* const* d_in, const int* in_sizes, int n_in,
                              void* d_out, int out_size)
{
    (void)in_sizes; (void)n_in; (void)out_size;
    const float* x  = (const float*)d_in[0];
    const float* ht = (const float*)d_in[1];
    const float* ct = (const float*)d_in[2];
    const float* wi = (const float*)d_in[3];
    const float* wh = (const float*)d_in[4];
    const float* bi = (const float*)d_in[5];
    const float* bh = (const float*)d_in[6];
    float* out = (float*)d_out;

    cudaFuncSetAttribute(lstm_gemm_mma, cudaFuncAttributeMaxDynamicSharedMemorySize, SMEM_TOTAL);

    convert_all<<<NBLK_A + 1024, 256>>>(x, ht, wi, wh, bi, bh);
    lstm_gemm_mma<<<dim3(4096 / BN, 4096 / BM), 256, SMEM_TOTAL>>>(ct, out);
}